// round 3
// baseline (speedup 1.0000x reference)
#include <cuda_runtime.h>
#include <float.h>
#include <math.h>

// Problem constants
#define B_    8
#define NPTS  8192
#define NS    2048
#define D1    128
#define D2    256
#define C1    384      // D1 + D2
#define C2    256
#define C3    128
#define MTOT  (B_ * NPTS)   // 65536

// ---------------------------------------------------------------------------
// Scratch (static device globals — no allocations allowed)
// ---------------------------------------------------------------------------
__device__ float  g_interp[(size_t)D2 * MTOT];   // 64 MB  interpolated features, [c2][m]
__device__ float  g_h1[(size_t)C2 * MTOT];       // 64 MB  GEMM1 out (pre-BN),   [c][m]
__device__ float  g_h2[(size_t)C3 * MTOT];       // 32 MB  GEMM2 out (pre-BN),   [c][m]
__device__ float2 g_ss1[C2];                     // BN1 (scale, shift)
__device__ float2 g_ss2[C3];                     // BN2 (scale, shift)

// ---------------------------------------------------------------------------
// Kernel 1: 3-NN search + inverse-distance interpolation (fused)
//   grid = B * (NPTS/256) = 256 blocks, 256 threads; one point per thread.
//   All 2048 sample positions (+precomputed |s|^2) live in 32KB smem as float4.
// ---------------------------------------------------------------------------
__global__ void __launch_bounds__(256) knn_interp_kernel(
    const float* __restrict__ pp,     // [B,3,N]
    const float* __restrict__ spp,    // [B,3,S]
    const float* __restrict__ sfeat)  // [B,D2,S]
{
    __shared__ float4 ssmp[NS];       // 32 KB

    const int b   = blockIdx.x >> 5;          // 32 blocks per batch
    const int n0  = (blockIdx.x & 31) << 8;
    const int tid = threadIdx.x;

    // Stage sample positions: (x, y, z, x^2+y^2+z^2)
    const float* sb = spp + (size_t)b * 3 * NS;
    for (int s = tid; s < NS; s += 256) {
        float x = sb[s], y = sb[s + NS], z = sb[s + 2 * NS];
        ssmp[s] = make_float4(x, y, z, fmaf(x, x, fmaf(y, y, z * z)));
    }
    __syncthreads();

    const int n = n0 + tid;
    const int m = b * NPTS + n;
    const float* pb = pp + (size_t)b * 3 * NPTS;
    const float px = pb[n], py = pb[n + NPTS], pz = pb[n + 2 * NPTS];

    // Track 3 smallest scores, score = |s|^2 - 2 p.s  (|p|^2 is a constant offset)
    float d0 = FLT_MAX, d1 = FLT_MAX, d2 = FLT_MAX;
    int   i0 = 0, i1 = 0, i2 = 0;

    #pragma unroll 4
    for (int j = 0; j < NS; j++) {
        float4 q   = ssmp[j];
        float  dot = fmaf(px, q.x, fmaf(py, q.y, pz * q.z));
        float  sc  = fmaf(-2.0f, dot, q.w);
        if (sc < d2) {
            if (sc < d1) {
                d2 = d1; i2 = i1;
                if (sc < d0) { d1 = d0; i1 = i0; d0 = sc; i0 = j; }
                else         { d1 = sc; i1 = j; }
            } else { d2 = sc; i2 = j; }
        }
    }

    const float p2 = fmaf(px, px, fmaf(py, py, pz * pz));
    float a0 = 1.0f / ((d0 + p2) + 1e-8f);
    float a1 = 1.0f / ((d1 + p2) + 1e-8f);
    float a2 = 1.0f / ((d2 + p2) + 1e-8f);
    const float inv = 1.0f / (a0 + a1 + a2);
    const float w0 = a0 * inv, w1 = a1 * inv, w2 = a2 * inv;

    // Interpolate all D2 channels; writes coalesced over m.
    const float* sf = sfeat + (size_t)b * ((size_t)D2 * NS);
    #pragma unroll 4
    for (int c = 0; c < D2; c++) {
        const float* row = sf + (size_t)c * NS;
        float v = fmaf(w0, __ldg(row + i0),
                  fmaf(w1, __ldg(row + i1),
                       w2 * __ldg(row + i2)));
        g_interp[(size_t)c * MTOT + m] = v;
    }
}

// ---------------------------------------------------------------------------
// Kernel 2: tiled SGEMM  C[i][j] = sum_k A[i][k] * Bsrc[k][j]
//   BM=BN=128, BK=16, 256 threads, 8x8 micro-tile.
//   mode 1: Bsrc rows k<128 read straight from skip [B,D1,N]; k>=128 from
//           g_interp. Out -> g_h1.  (skip half of the concat never materialized)
//   mode 2: Bsrc = relu(g_h1 * scale1 + shift1) fused on load. Out -> g_h2.
// ---------------------------------------------------------------------------
__global__ void __launch_bounds__(256) sgemm_kernel(
    const float* __restrict__ A,      // [Mo, K] row-major
    const float* __restrict__ skip,   // [B, D1, N] (mode 1 only)
    int K, int mode)
{
    __shared__ float As[16][128];
    __shared__ float Bs[16][128];

    const int tid = threadIdx.x;
    const int j0  = blockIdx.x * 128;
    const int i0  = blockIdx.y * 128;
    const int tx  = tid & 15;
    const int ty  = tid >> 4;

    // A-load: thread covers rows {ar, ar+64}, k-offset ak..ak+3
    const int ar = tid >> 2;
    const int ak = (tid & 3) << 2;
    // B-load: thread covers k-rows {br, br+8}, columns bj..bj+3
    const int br = tid >> 5;
    const int bj = (tid & 31) << 2;

    const int bb  = j0 / NPTS;   // batch of this column tile (128 | 8192)
    const int nn0 = j0 % NPTS;

    float acc[8][8];
    #pragma unroll
    for (int i = 0; i < 8; i++)
        #pragma unroll
        for (int j = 0; j < 8; j++) acc[i][j] = 0.0f;

    for (int kt = 0; kt < K; kt += 16) {
        // --- load A tile (transposed into As[k][i]) ---
        #pragma unroll
        for (int p = 0; p < 2; p++) {
            int row = ar + p * 64;
            float4 v = *(const float4*)(A + (size_t)(i0 + row) * K + kt + ak);
            As[ak + 0][row] = v.x;
            As[ak + 1][row] = v.y;
            As[ak + 2][row] = v.z;
            As[ak + 3][row] = v.w;
        }
        // --- load B tile ---
        #pragma unroll
        for (int p = 0; p < 2; p++) {
            int kk = kt + br + p * 8;
            float4 v;
            if (mode == 1) {
                const float* src = (kk < D1)
                    ? skip     + ((size_t)bb * D1 + kk) * NPTS + nn0 + bj
                    : g_interp + (size_t)(kk - D1) * MTOT + j0 + bj;
                v = *(const float4*)src;
            } else {
                v = *(const float4*)(g_h1 + (size_t)kk * MTOT + j0 + bj);
                float2 ss = g_ss1[kk];
                v.x = fmaxf(fmaf(v.x, ss.x, ss.y), 0.0f);
                v.y = fmaxf(fmaf(v.y, ss.x, ss.y), 0.0f);
                v.z = fmaxf(fmaf(v.z, ss.x, ss.y), 0.0f);
                v.w = fmaxf(fmaf(v.w, ss.x, ss.y), 0.0f);
            }
            *(float4*)&Bs[br + p * 8][bj] = v;
        }
        __syncthreads();

        // --- compute ---
        #pragma unroll
        for (int k = 0; k < 16; k++) {
            float af[8], bf[8];
            *(float4*)(af)     = *(const float4*)&As[k][ty * 8];
            *(float4*)(af + 4) = *(const float4*)&As[k][ty * 8 + 4];
            *(float4*)(bf)     = *(const float4*)&Bs[k][tx * 8];
            *(float4*)(bf + 4) = *(const float4*)&Bs[k][tx * 8 + 4];
            #pragma unroll
            for (int i = 0; i < 8; i++)
                #pragma unroll
                for (int j = 0; j < 8; j++)
                    acc[i][j] = fmaf(af[i], bf[j], acc[i][j]);
        }
        __syncthreads();
    }

    float* dst = (mode == 1) ? g_h1 : g_h2;
    #pragma unroll
    for (int i = 0; i < 8; i++) {
        float* d = dst + (size_t)(i0 + ty * 8 + i) * MTOT + j0 + tx * 8;
        *(float4*)(d)     = *(float4*)&acc[i][0];
        *(float4*)(d + 4) = *(float4*)&acc[i][4];
    }
}

// ---------------------------------------------------------------------------
// Kernel 3: BatchNorm stats -> per-channel (scale, shift)
//   One block per channel. Double-precision block reduction.
//   Bias terms cancel exactly inside BN, so GEMMs run bias-free.
// ---------------------------------------------------------------------------
__global__ void __launch_bounds__(256) bn_stats_kernel(
    const float* __restrict__ g, const float* __restrict__ beta, int which)
{
    const int c   = blockIdx.x;
    const int tid = threadIdx.x;
    const float* H = (which == 1) ? g_h1 : g_h2;
    const float4* p = (const float4*)(H + (size_t)c * MTOT);

    float s = 0.0f, sq = 0.0f;
    #pragma unroll 4
    for (int i = 0; i < MTOT / 4 / 256; i++) {     // 64 iterations
        float4 v = p[tid + i * 256];
        s  += v.x + v.y + v.z + v.w;
        sq += v.x * v.x + v.y * v.y + v.z * v.z + v.w * v.w;
    }

    __shared__ double r1[256], r2[256];
    r1[tid] = (double)s;
    r2[tid] = (double)sq;
    __syncthreads();
    for (int o = 128; o > 0; o >>= 1) {
        if (tid < o) { r1[tid] += r1[tid + o]; r2[tid] += r2[tid + o]; }
        __syncthreads();
    }
    if (tid == 0) {
        double mean = r1[0] / (double)MTOT;
        double var  = r2[0] / (double)MTOT - mean * mean;
        double rs   = 1.0 / sqrt(var + 1e-5);
        float scale = (float)((double)g[c] * rs);
        float shift = (float)((double)beta[c] - mean * (double)g[c] * rs);
        if (which == 1) g_ss1[c] = make_float2(scale, shift);
        else            g_ss2[c] = make_float2(scale, shift);
    }
}

// ---------------------------------------------------------------------------
// Kernel 4: final BN2 + ReLU + layout transform [c][b*N+n] -> [b][c][n]
// ---------------------------------------------------------------------------
__global__ void __launch_bounds__(256) bn_out_kernel(float* __restrict__ out)
{
    size_t f = (size_t)blockIdx.x * blockDim.x + threadIdx.x;  // float4 index
    size_t e = f * 4;
    int c = (int)(e / MTOT);
    int m = (int)(e % MTOT);
    int b = m / NPTS;
    int n = m % NPTS;

    float4 v = ((const float4*)g_h2)[f];
    float2 ss = g_ss2[c];
    v.x = fmaxf(fmaf(v.x, ss.x, ss.y), 0.0f);
    v.y = fmaxf(fmaf(v.y, ss.x, ss.y), 0.0f);
    v.z = fmaxf(fmaf(v.z, ss.x, ss.y), 0.0f);
    v.w = fmaxf(fmaf(v.w, ss.x, ss.y), 0.0f);
    *(float4*)(out + ((size_t)b * C3 + c) * NPTS + n) = v;
}

// ---------------------------------------------------------------------------
// Launcher
// ---------------------------------------------------------------------------
extern "C" void kernel_launch(void* const* d_in, const int* in_sizes, int n_in,
                              void* d_out, int out_size)
{
    const float* pp    = (const float*)d_in[0];   // points_position       [8,3,8192]
    const float* spp   = (const float*)d_in[1];   // sampled_points_pos    [8,3,2048]
    const float* skip  = (const float*)d_in[2];   // skip_points_feature   [8,128,8192]
    const float* sfeat = (const float*)d_in[3];   // sampled_points_feat   [8,256,2048]
    const float* W1    = (const float*)d_in[4];   // [256,384]
    // d_in[5] = b1 (cancels inside BN — unused)
    const float* g1    = (const float*)d_in[6];
    const float* be1   = (const float*)d_in[7];
    const float* W2    = (const float*)d_in[8];   // [128,256]
    // d_in[9] = b2 (cancels inside BN — unused)
    const float* g2    = (const float*)d_in[10];
    const float* be2   = (const float*)d_in[11];
    float* out = (float*)d_out;

    // 1) 3-NN + interpolation
    knn_interp_kernel<<<B_ * (NPTS / 256), 256>>>(pp, spp, sfeat);

    // 2) GEMM1: H1 = W1 @ [skip ; interp]   (256 x 65536, K=384)
    {
        dim3 grid(MTOT / 128, C2 / 128);
        sgemm_kernel<<<grid, 256>>>(W1, skip, C1, 1);
    }

    // 3) BN1 stats
    bn_stats_kernel<<<C2, 256>>>(g1, be1, 1);

    // 4) GEMM2: H2 = W2 @ relu(BN1(H1))     (128 x 65536, K=256, BN fused on load)
    {
        dim3 grid(MTOT / 128, C3 / 128);
        sgemm_kernel<<<grid, 256>>>(W2, nullptr, C2, 2);
    }

    // 5) BN2 stats
    bn_stats_kernel<<<C3, 256>>>(g2, be2, 2);

    // 6) BN2 apply + ReLU + transpose to [B,128,N]
    bn_out_kernel<<<(C3 * MTOT / 4) / 256, 256>>>(out);
}

// round 4
// speedup vs baseline: 1.5799x; 1.5799x over previous
#include <cuda_runtime.h>
#include <float.h>
#include <math.h>

// Problem constants
#define B_    8
#define NPTS  8192
#define NS    2048
#define D1    128
#define D2    256
#define C1    384      // D1 + D2
#define C2    256
#define C3    128
#define MTOT  (B_ * NPTS)   // 65536

// ---------------------------------------------------------------------------
// Scratch (static device globals — no allocations allowed)
// ---------------------------------------------------------------------------
__device__ float  g_interp[(size_t)D2 * MTOT];   // 64 MB  interpolated features [c][m]
__device__ float  g_h1[(size_t)C2 * MTOT];       // 64 MB  GEMM1 out (pre-BN)    [c][m]
__device__ float  g_h2[(size_t)C3 * MTOT];       // 32 MB  GEMM2 out (pre-BN)    [c][m]
__device__ float  g_sfT[(size_t)B_ * NS * D2];   // 16 MB  sfeat transposed [b][s][c]
__device__ float4 g_w[MTOT];                     // per-point 3-NN weights
__device__ int4   g_i[MTOT];                     // per-point 3-NN indices
__device__ float2 g_ss1[C2];                     // BN1 (scale, shift)
__device__ float2 g_ss2[C3];                     // BN2 (scale, shift)

// ---------------------------------------------------------------------------
// Kernel 1: 3-NN search (indices + normalized inverse-distance weights only)
// ---------------------------------------------------------------------------
__global__ void __launch_bounds__(256) knn_kernel(
    const float* __restrict__ pp,     // [B,3,N]
    const float* __restrict__ spp)    // [B,3,S]
{
    __shared__ float4 ssmp[NS];       // 32 KB

    const int b   = blockIdx.x >> 5;          // 32 blocks per batch
    const int n0  = (blockIdx.x & 31) << 8;
    const int tid = threadIdx.x;

    const float* sb = spp + (size_t)b * 3 * NS;
    for (int s = tid; s < NS; s += 256) {
        float x = sb[s], y = sb[s + NS], z = sb[s + 2 * NS];
        ssmp[s] = make_float4(x, y, z, fmaf(x, x, fmaf(y, y, z * z)));
    }
    __syncthreads();

    const int n = n0 + tid;
    const int m = b * NPTS + n;
    const float* pb = pp + (size_t)b * 3 * NPTS;
    const float px = pb[n], py = pb[n + NPTS], pz = pb[n + 2 * NPTS];

    // score = |s|^2 - 2 p.s  (|p|^2 is a constant offset, added back at the end)
    float d0 = FLT_MAX, d1 = FLT_MAX, d2 = FLT_MAX;
    int   i0 = 0, i1 = 0, i2 = 0;

    #pragma unroll 4
    for (int j = 0; j < NS; j++) {
        float4 q   = ssmp[j];
        float  dot = fmaf(px, q.x, fmaf(py, q.y, pz * q.z));
        float  sc  = fmaf(-2.0f, dot, q.w);
        if (sc < d2) {
            if (sc < d1) {
                d2 = d1; i2 = i1;
                if (sc < d0) { d1 = d0; i1 = i0; d0 = sc; i0 = j; }
                else         { d1 = sc; i1 = j; }
            } else { d2 = sc; i2 = j; }
        }
    }

    const float p2 = fmaf(px, px, fmaf(py, py, pz * pz));
    float a0 = 1.0f / ((d0 + p2) + 1e-8f);
    float a1 = 1.0f / ((d1 + p2) + 1e-8f);
    float a2 = 1.0f / ((d2 + p2) + 1e-8f);
    const float inv = 1.0f / (a0 + a1 + a2);

    g_w[m] = make_float4(a0 * inv, a1 * inv, a2 * inv, 0.0f);
    g_i[m] = make_int4(i0, i1, i2, 0);
}

// ---------------------------------------------------------------------------
// Kernel 1b: transpose sfeat [b][c][s] -> g_sfT [b][s][c]   (16 MB, tiled)
// ---------------------------------------------------------------------------
__global__ void __launch_bounds__(256) transpose_sfeat_kernel(
    const float* __restrict__ sfeat)
{
    __shared__ float tile[32][33];
    const int b  = blockIdx.z;
    const int s0 = blockIdx.x * 32;
    const int c0 = blockIdx.y * 32;
    const int tx = threadIdx.x;      // 0..31
    const int ty = threadIdx.y;      // 0..7

    #pragma unroll
    for (int r = 0; r < 32; r += 8)
        tile[ty + r][tx] = sfeat[((size_t)b * D2 + c0 + ty + r) * NS + s0 + tx];
    __syncthreads();
    #pragma unroll
    for (int r = 0; r < 32; r += 8)
        g_sfT[((size_t)b * NS + s0 + ty + r) * D2 + c0 + tx] = tile[tx][ty + r];
}

// ---------------------------------------------------------------------------
// Kernel 2: interpolation. Block = 32 points, 256 threads.
//   Gather: thread t reads channel c=t of each neighbor row (fully coalesced
//   1KB loads from g_sfT). Padded smem tile turns the [c][m] output into
//   coalesced float4 stores.
// ---------------------------------------------------------------------------
__global__ void __launch_bounds__(256) interp_kernel()
{
    __shared__ float  st[D2][33];    // +1 pad: conflict-free both phases
    __shared__ float4 sw[32];
    __shared__ int4   si[32];

    const int m0  = blockIdx.x * 32;
    const int b   = m0 / NPTS;       // 32 | NPTS -> one batch per block
    const int tid = threadIdx.x;

    if (tid < 32) { sw[tid] = g_w[m0 + tid]; si[tid] = g_i[m0 + tid]; }
    __syncthreads();

    const float* fT = g_sfT + (size_t)b * NS * D2;
    #pragma unroll 4
    for (int p = 0; p < 32; p++) {
        float4 w = sw[p];
        int4   ii = si[p];
        float v = fmaf(w.x, __ldg(fT + (size_t)ii.x * D2 + tid),
                  fmaf(w.y, __ldg(fT + (size_t)ii.y * D2 + tid),
                       w.z * __ldg(fT + (size_t)ii.z * D2 + tid)));
        st[tid][p] = v;
    }
    __syncthreads();

    const int c8 = tid >> 3;         // 0..31
    const int j  = (tid & 7) << 2;   // 0,4,...,28
    #pragma unroll
    for (int r = 0; r < 8; r++) {
        int c = r * 32 + c8;
        float4 v = make_float4(st[c][j], st[c][j + 1], st[c][j + 2], st[c][j + 3]);
        *(float4*)&g_interp[(size_t)c * MTOT + m0 + j] = v;
    }
}

// ---------------------------------------------------------------------------
// Kernel 3: double-buffered tiled SGEMM  C[i][j] = sum_k A[i][k] * Bsrc[k][j]
//   BM=BN=128, BK=16, 256 threads, 8x8 micro-tile, reg-prefetch + 2x smem.
//   mode 1: Bsrc k<128 straight from skip [B,D1,N]; k>=128 from g_interp.
//   mode 2: Bsrc = relu(g_h1 * scale1 + shift1) fused on load.
// ---------------------------------------------------------------------------
__global__ void __launch_bounds__(256, 2) sgemm_kernel(
    const float* __restrict__ A,      // [Mo, K] row-major
    const float* __restrict__ skip,   // [B, D1, N] (mode 1 only)
    int K, int mode)
{
    __shared__ float As[2][16][128];
    __shared__ float Bs[2][16][128];

    const int tid = threadIdx.x;
    const int j0  = blockIdx.x * 128;
    const int i0  = blockIdx.y * 128;
    const int tx  = tid & 15;
    const int ty  = tid >> 4;

    const int ar = tid >> 2;          // A rows {ar, ar+64}
    const int ak = (tid & 3) << 2;    // A k-offset
    const int br = tid >> 5;          // B k-rows {br, br+8}
    const int bj = (tid & 31) << 2;   // B columns

    const int bb  = j0 / NPTS;
    const int nn0 = j0 % NPTS;

    float acc[8][8];
    #pragma unroll
    for (int i = 0; i < 8; i++)
        #pragma unroll
        for (int j = 0; j < 8; j++) acc[i][j] = 0.0f;

    float4 pa0, pa1, pb0, pb1;

    // ---- tile loaders (global -> registers) ----
    #define LDG_TILE(kt)                                                        \
    {                                                                           \
        pa0 = *(const float4*)(A + (size_t)(i0 + ar)      * K + (kt) + ak);     \
        pa1 = *(const float4*)(A + (size_t)(i0 + ar + 64) * K + (kt) + ak);     \
        int kk0 = (kt) + br;                                                    \
        int kk1 = kk0 + 8;                                                      \
        if (mode == 1) {                                                        \
            const float* s0 = (kk0 < D1)                                        \
                ? skip     + ((size_t)bb * D1 + kk0) * NPTS + nn0 + bj          \
                : g_interp + (size_t)(kk0 - D1) * MTOT + j0 + bj;               \
            const float* s1 = (kk1 < D1)                                        \
                ? skip     + ((size_t)bb * D1 + kk1) * NPTS + nn0 + bj          \
                : g_interp + (size_t)(kk1 - D1) * MTOT + j0 + bj;               \
            pb0 = *(const float4*)s0;                                           \
            pb1 = *(const float4*)s1;                                           \
        } else {                                                                \
            pb0 = *(const float4*)(g_h1 + (size_t)kk0 * MTOT + j0 + bj);        \
            pb1 = *(const float4*)(g_h1 + (size_t)kk1 * MTOT + j0 + bj);        \
            float2 s0 = g_ss1[kk0], s1 = g_ss1[kk1];                            \
            pb0.x = fmaxf(fmaf(pb0.x, s0.x, s0.y), 0.0f);                       \
            pb0.y = fmaxf(fmaf(pb0.y, s0.x, s0.y), 0.0f);                       \
            pb0.z = fmaxf(fmaf(pb0.z, s0.x, s0.y), 0.0f);                       \
            pb0.w = fmaxf(fmaf(pb0.w, s0.x, s0.y), 0.0f);                       \
            pb1.x = fmaxf(fmaf(pb1.x, s1.x, s1.y), 0.0f);                       \
            pb1.y = fmaxf(fmaf(pb1.y, s1.x, s1.y), 0.0f);                       \
            pb1.z = fmaxf(fmaf(pb1.z, s1.x, s1.y), 0.0f);                       \
            pb1.w = fmaxf(fmaf(pb1.w, s1.x, s1.y), 0.0f);                       \
        }                                                                       \
    }

    #define STS_TILE(buf)                                                      \
    {                                                                          \
        As[buf][ak + 0][ar] = pa0.x;  As[buf][ak + 1][ar] = pa0.y;             \
        As[buf][ak + 2][ar] = pa0.z;  As[buf][ak + 3][ar] = pa0.w;             \
        As[buf][ak + 0][ar + 64] = pa1.x;  As[buf][ak + 1][ar + 64] = pa1.y;   \
        As[buf][ak + 2][ar + 64] = pa1.z;  As[buf][ak + 3][ar + 64] = pa1.w;   \
        *(float4*)&Bs[buf][br][bj]     = pb0;                                  \
        *(float4*)&Bs[buf][br + 8][bj] = pb1;                                  \
    }

    #define COMPUTE(buf)                                                       \
    {                                                                          \
        _Pragma("unroll")                                                      \
        for (int k = 0; k < 16; k++) {                                         \
            float af[8], bf[8];                                                \
            *(float4*)(af)     = *(const float4*)&As[buf][k][ty * 8];          \
            *(float4*)(af + 4) = *(const float4*)&As[buf][k][ty * 8 + 4];      \
            *(float4*)(bf)     = *(const float4*)&Bs[buf][k][tx * 8];          \
            *(float4*)(bf + 4) = *(const float4*)&Bs[buf][k][tx * 8 + 4];      \
            _Pragma("unroll")                                                  \
            for (int i = 0; i < 8; i++)                                        \
                _Pragma("unroll")                                              \
                for (int j = 0; j < 8; j++)                                    \
                    acc[i][j] = fmaf(af[i], bf[j], acc[i][j]);                 \
        }                                                                      \
    }

    LDG_TILE(0);
    STS_TILE(0);
    __syncthreads();

    int buf = 0;
    for (int kt = 16; kt < K; kt += 16) {
        LDG_TILE(kt);            // prefetch next tile (latency hidden by compute)
        COMPUTE(buf);
        STS_TILE(buf ^ 1);
        __syncthreads();
        buf ^= 1;
    }
    COMPUTE(buf);

    float* dst = (mode == 1) ? g_h1 : g_h2;
    #pragma unroll
    for (int i = 0; i < 8; i++) {
        float* d = dst + (size_t)(i0 + ty * 8 + i) * MTOT + j0 + tx * 8;
        *(float4*)(d)     = *(float4*)&acc[i][0];
        *(float4*)(d + 4) = *(float4*)&acc[i][4];
    }
    #undef LDG_TILE
    #undef STS_TILE
    #undef COMPUTE
}

// ---------------------------------------------------------------------------
// Kernel 4: BatchNorm stats -> per-channel (scale, shift).
//   One block per channel, double-precision block reduction.
//   Bias terms cancel exactly inside BN, so GEMMs run bias-free.
// ---------------------------------------------------------------------------
__global__ void __launch_bounds__(256) bn_stats_kernel(
    const float* __restrict__ g, const float* __restrict__ beta, int which)
{
    const int c   = blockIdx.x;
    const int tid = threadIdx.x;
    const float* H = (which == 1) ? g_h1 : g_h2;
    const float4* p = (const float4*)(H + (size_t)c * MTOT);

    float s = 0.0f, sq = 0.0f;
    #pragma unroll 4
    for (int i = 0; i < MTOT / 4 / 256; i++) {
        float4 v = p[tid + i * 256];
        s  += v.x + v.y + v.z + v.w;
        sq += v.x * v.x + v.y * v.y + v.z * v.z + v.w * v.w;
    }

    __shared__ double r1[256], r2[256];
    r1[tid] = (double)s;
    r2[tid] = (double)sq;
    __syncthreads();
    for (int o = 128; o > 0; o >>= 1) {
        if (tid < o) { r1[tid] += r1[tid + o]; r2[tid] += r2[tid + o]; }
        __syncthreads();
    }
    if (tid == 0) {
        double mean = r1[0] / (double)MTOT;
        double var  = r2[0] / (double)MTOT - mean * mean;
        double rs   = 1.0 / sqrt(var + 1e-5);
        float scale = (float)((double)g[c] * rs);
        float shift = (float)((double)beta[c] - mean * (double)g[c] * rs);
        if (which == 1) g_ss1[c] = make_float2(scale, shift);
        else            g_ss2[c] = make_float2(scale, shift);
    }
}

// ---------------------------------------------------------------------------
// Kernel 5: final BN2 + ReLU + layout transform [c][b*N+n] -> [b][c][n]
// ---------------------------------------------------------------------------
__global__ void __launch_bounds__(256) bn_out_kernel(float* __restrict__ out)
{
    size_t f = (size_t)blockIdx.x * blockDim.x + threadIdx.x;  // float4 index
    size_t e = f * 4;
    int c = (int)(e / MTOT);
    int m = (int)(e % MTOT);
    int b = m / NPTS;
    int n = m % NPTS;

    float4 v = ((const float4*)g_h2)[f];
    float2 ss = g_ss2[c];
    v.x = fmaxf(fmaf(v.x, ss.x, ss.y), 0.0f);
    v.y = fmaxf(fmaf(v.y, ss.x, ss.y), 0.0f);
    v.z = fmaxf(fmaf(v.z, ss.x, ss.y), 0.0f);
    v.w = fmaxf(fmaf(v.w, ss.x, ss.y), 0.0f);
    *(float4*)(out + ((size_t)b * C3 + c) * NPTS + n) = v;
}

// ---------------------------------------------------------------------------
// Launcher
// ---------------------------------------------------------------------------
extern "C" void kernel_launch(void* const* d_in, const int* in_sizes, int n_in,
                              void* d_out, int out_size)
{
    const float* pp    = (const float*)d_in[0];   // [8,3,8192]
    const float* spp   = (const float*)d_in[1];   // [8,3,2048]
    const float* skip  = (const float*)d_in[2];   // [8,128,8192]
    const float* sfeat = (const float*)d_in[3];   // [8,256,2048]
    const float* W1    = (const float*)d_in[4];   // [256,384]
    // d_in[5] = b1 (cancels inside BN)
    const float* g1    = (const float*)d_in[6];
    const float* be1   = (const float*)d_in[7];
    const float* W2    = (const float*)d_in[8];   // [128,256]
    // d_in[9] = b2 (cancels inside BN)
    const float* g2    = (const float*)d_in[10];
    const float* be2   = (const float*)d_in[11];
    float* out = (float*)d_out;

    // 1) 3-NN indices/weights + sfeat transpose
    knn_kernel<<<B_ * (NPTS / 256), 256>>>(pp, spp);
    {
        dim3 grid(NS / 32, D2 / 32, B_), blk(32, 8);
        transpose_sfeat_kernel<<<grid, blk>>>(sfeat);
    }

    // 2) coalesced interpolation -> g_interp [c][m]
    interp_kernel<<<MTOT / 32, 256>>>();

    // 3) GEMM1: H1 = W1 @ [skip ; interp]   (256 x 65536, K=384)
    {
        dim3 grid(MTOT / 128, C2 / 128);
        sgemm_kernel<<<grid, 256>>>(W1, skip, C1, 1);
    }

    // 4) BN1 stats
    bn_stats_kernel<<<C2, 256>>>(g1, be1, 1);

    // 5) GEMM2: H2 = W2 @ relu(BN1(H1))     (128 x 65536, K=256, BN fused on load)
    {
        dim3 grid(MTOT / 128, C3 / 128);
        sgemm_kernel<<<grid, 256>>>(W2, nullptr, C2, 2);
    }

    // 6) BN2 stats
    bn_stats_kernel<<<C3, 256>>>(g2, be2, 2);

    // 7) BN2 apply + ReLU + transpose to [B,128,N]
    bn_out_kernel<<<(C3 * MTOT / 4) / 256, 256>>>(out);
}

// round 6
// speedup vs baseline: 2.1493x; 1.3604x over previous
#include <cuda_runtime.h>
#include <cuda_bf16.h>
#include <float.h>
#include <math.h>
#include <stdint.h>

// Problem constants
#define B_    8
#define NPTS  8192
#define NS    2048
#define D1    128
#define D2    256
#define C1    384      // D1 + D2
#define C2    256
#define C3    128
#define MTOT  (B_ * NPTS)   // 65536

// ---------------------------------------------------------------------------
// Scratch (static device globals — no allocations allowed)
// ---------------------------------------------------------------------------
__device__ float  g_interp[(size_t)D2 * MTOT];   // 64 MB  interpolated features [c][m]
__device__ float  g_h1[(size_t)C2 * MTOT];       // 64 MB  GEMM1 out (pre-BN)    [c][m]
__device__ float  g_h2[(size_t)C3 * MTOT];       // 32 MB  GEMM2 out (pre-BN)    [c][m]
__device__ float  g_sfT[(size_t)B_ * NS * D2];   // 16 MB  sfeat transposed [b][s][c]
__device__ float4 g_w[MTOT];                     // per-point 3-NN weights
__device__ int4   g_i[MTOT];                     // per-point 3-NN indices
__device__ float2 g_ss1[C2];                     // BN1 (scale, shift)
__device__ float2 g_ss2[C3];                     // BN2 (scale, shift)
// split-bf16 weights (hi + lo planes), row-major [o][k]; 16B-aligned for uint4
__device__ __align__(16) __nv_bfloat16 g_W1hi[C2 * C1], g_W1lo[C2 * C1];
__device__ __align__(16) __nv_bfloat16 g_W2hi[C3 * C2], g_W2lo[C3 * C2];

// ---------------------------------------------------------------------------
// bf16 split helpers
// ---------------------------------------------------------------------------
__device__ __forceinline__ void bf16_split(float x, __nv_bfloat16& h, __nv_bfloat16& l) {
    h = __float2bfloat16_rn(x);
    l = __float2bfloat16_rn(x - __bfloat162float(h));
}
__device__ __forceinline__ uint32_t pack2(__nv_bfloat16 a, __nv_bfloat16 b) {
    __nv_bfloat162 p = __nv_bfloat162(a, b);  // a -> low half
    return *reinterpret_cast<uint32_t*>(&p);
}

__device__ __forceinline__ void mma16816(float* d, const uint32_t* a, const uint32_t* b) {
    asm volatile(
        "mma.sync.aligned.m16n8k16.row.col.f32.bf16.bf16.f32 "
        "{%0,%1,%2,%3}, {%4,%5,%6,%7}, {%8,%9}, {%0,%1,%2,%3};\n"
        : "+f"(d[0]), "+f"(d[1]), "+f"(d[2]), "+f"(d[3])
        : "r"(a[0]), "r"(a[1]), "r"(a[2]), "r"(a[3]), "r"(b[0]), "r"(b[1]));
}

// ---------------------------------------------------------------------------
// Kernel 0: split weights into bf16 hi/lo planes
// ---------------------------------------------------------------------------
__global__ void __launch_bounds__(256) prep_weights_kernel(
    const float* __restrict__ W1, const float* __restrict__ W2)
{
    int i = blockIdx.x * 256 + threadIdx.x;
    if (i < C2 * C1) { __nv_bfloat16 h, l; bf16_split(W1[i], h, l); g_W1hi[i] = h; g_W1lo[i] = l; }
    if (i < C3 * C2) { __nv_bfloat16 h, l; bf16_split(W2[i], h, l); g_W2hi[i] = h; g_W2lo[i] = l; }
}

// ---------------------------------------------------------------------------
// Kernel 1: 3-NN search (indices + normalized inverse-distance weights)
// ---------------------------------------------------------------------------
__global__ void __launch_bounds__(256) knn_kernel(
    const float* __restrict__ pp,     // [B,3,N]
    const float* __restrict__ spp)    // [B,3,S]
{
    __shared__ float4 ssmp[NS];       // 32 KB

    const int b   = blockIdx.x >> 5;
    const int n0  = (blockIdx.x & 31) << 8;
    const int tid = threadIdx.x;

    const float* sb = spp + (size_t)b * 3 * NS;
    for (int s = tid; s < NS; s += 256) {
        float x = sb[s], y = sb[s + NS], z = sb[s + 2 * NS];
        ssmp[s] = make_float4(x, y, z, fmaf(x, x, fmaf(y, y, z * z)));
    }
    __syncthreads();

    const int n = n0 + tid;
    const int m = b * NPTS + n;
    const float* pb = pp + (size_t)b * 3 * NPTS;
    const float px = pb[n], py = pb[n + NPTS], pz = pb[n + 2 * NPTS];

    float d0 = FLT_MAX, d1 = FLT_MAX, d2 = FLT_MAX;
    int   i0 = 0, i1 = 0, i2 = 0;

    #pragma unroll 4
    for (int j = 0; j < NS; j++) {
        float4 q   = ssmp[j];
        float  dot = fmaf(px, q.x, fmaf(py, q.y, pz * q.z));
        float  sc  = fmaf(-2.0f, dot, q.w);
        if (sc < d2) {
            if (sc < d1) {
                d2 = d1; i2 = i1;
                if (sc < d0) { d1 = d0; i1 = i0; d0 = sc; i0 = j; }
                else         { d1 = sc; i1 = j; }
            } else { d2 = sc; i2 = j; }
        }
    }

    const float p2 = fmaf(px, px, fmaf(py, py, pz * pz));
    float a0 = 1.0f / ((d0 + p2) + 1e-8f);
    float a1 = 1.0f / ((d1 + p2) + 1e-8f);
    float a2 = 1.0f / ((d2 + p2) + 1e-8f);
    const float inv = 1.0f / (a0 + a1 + a2);

    g_w[m] = make_float4(a0 * inv, a1 * inv, a2 * inv, 0.0f);
    g_i[m] = make_int4(i0, i1, i2, 0);
}

// ---------------------------------------------------------------------------
// Kernel 1b: transpose sfeat [b][c][s] -> g_sfT [b][s][c]
// ---------------------------------------------------------------------------
__global__ void __launch_bounds__(256) transpose_sfeat_kernel(
    const float* __restrict__ sfeat)
{
    __shared__ float tile[32][33];
    const int b  = blockIdx.z;
    const int s0 = blockIdx.x * 32;
    const int c0 = blockIdx.y * 32;
    const int tx = threadIdx.x;
    const int ty = threadIdx.y;

    #pragma unroll
    for (int r = 0; r < 32; r += 8)
        tile[ty + r][tx] = sfeat[((size_t)b * D2 + c0 + ty + r) * NS + s0 + tx];
    __syncthreads();
    #pragma unroll
    for (int r = 0; r < 32; r += 8)
        g_sfT[((size_t)b * NS + s0 + ty + r) * D2 + c0 + tx] = tile[tx][ty + r];
}

// ---------------------------------------------------------------------------
// Kernel 2: coalesced interpolation -> g_interp [c][m]
// ---------------------------------------------------------------------------
__global__ void __launch_bounds__(256) interp_kernel()
{
    __shared__ float  st[D2][33];
    __shared__ float4 sw[32];
    __shared__ int4   si[32];

    const int m0  = blockIdx.x * 32;
    const int b   = m0 / NPTS;
    const int tid = threadIdx.x;

    if (tid < 32) { sw[tid] = g_w[m0 + tid]; si[tid] = g_i[m0 + tid]; }
    __syncthreads();

    const float* fT = g_sfT + (size_t)b * NS * D2;
    #pragma unroll 4
    for (int p = 0; p < 32; p++) {
        float4 w = sw[p];
        int4   ii = si[p];
        float v = fmaf(w.x, __ldg(fT + (size_t)ii.x * D2 + tid),
                  fmaf(w.y, __ldg(fT + (size_t)ii.y * D2 + tid),
                       w.z * __ldg(fT + (size_t)ii.z * D2 + tid)));
        st[tid][p] = v;
    }
    __syncthreads();

    const int c8 = tid >> 3;
    const int j  = (tid & 7) << 2;
    #pragma unroll
    for (int r = 0; r < 8; r++) {
        int c = r * 32 + c8;
        float4 v = make_float4(st[c][j], st[c][j + 1], st[c][j + 2], st[c][j + 3]);
        *(float4*)&g_interp[(size_t)c * MTOT + m0 + j] = v;
    }
}

// ---------------------------------------------------------------------------
// Kernel 3: tensor-core GEMM, bf16 split x3 (hi*hi + hi*lo + lo*hi).
//   C[i][j] = sum_k W[i][k] * Bsrc[k][j]
//   128x128 tile, BK=16, 8 warps (2x4), warp tile 64x32, mma.m16n8k16.
//   Weights selected INSIDE the kernel from `mode` (device globals must not
//   be passed as arguments from host code — that was R5's bug).
//   mode 1: W1 planes; Bsrc k<128 from skip, k>=128 from g_interp. Out g_h1.
//   mode 2: W2 planes; Bsrc = relu(g_h1*scale1+shift1) fused.      Out g_h2.
// ---------------------------------------------------------------------------
__global__ void __launch_bounds__(256) mma_gemm_kernel(
    const float* __restrict__ skip,   // mode 1 only
    int K, int mode)
{
    __shared__ uint32_t As_hi[2][128 * 8];   // [m][kpair]
    __shared__ uint32_t As_lo[2][128 * 8];
    __shared__ uint32_t Bs_hi[2][8 * 128];   // [kpair][n] (col ^ (kp<<3) swizzle)
    __shared__ uint32_t Bs_lo[2][8 * 128];

    const __nv_bfloat16* __restrict__ Whi = (mode == 1) ? g_W1hi : g_W2hi;
    const __nv_bfloat16* __restrict__ Wlo = (mode == 1) ? g_W1lo : g_W2lo;

    const int tid  = threadIdx.x;
    const int lane = tid & 31;
    const int wid  = tid >> 5;
    const int wm   = wid >> 2;        // 0..1
    const int wn   = wid & 3;         // 0..3
    const int g    = lane >> 2;       // 0..7
    const int t    = lane & 3;        // 0..3

    const int j0 = blockIdx.x * 128;
    const int i0 = blockIdx.y * 128;

    const int arow = tid >> 1;            // A: row 0..127
    const int akh  = tid & 1;             // A: k-half (8 bf16)
    const int brp  = tid >> 5;            // B: k-pair row 0..7
    const int bc0  = lane * 4;            // B: col group

    const int bb  = j0 / NPTS;
    const int nn0 = j0 % NPTS;

    float acc[4][4][4];
    #pragma unroll
    for (int mt = 0; mt < 4; mt++)
        #pragma unroll
        for (int nt = 0; nt < 4; nt++)
            #pragma unroll
            for (int e = 0; e < 4; e++) acc[mt][nt][e] = 0.0f;

    uint4  ra_hi, ra_lo;
    float4 rb0, rb1;

    #define LDG_TILE(kt)                                                         \
    {                                                                            \
        ra_hi = *(const uint4*)(Whi + (size_t)(i0 + arow) * K + (kt) + akh * 8); \
        ra_lo = *(const uint4*)(Wlo + (size_t)(i0 + arow) * K + (kt) + akh * 8); \
        int k0 = (kt) + brp * 2;                                                 \
        if (mode == 1) {                                                         \
            const float* s0; size_t stride;                                      \
            if (k0 < D1) { s0 = skip + ((size_t)bb * D1 + k0) * NPTS + nn0 + bc0; stride = NPTS; } \
            else         { s0 = g_interp + (size_t)(k0 - D1) * MTOT + j0 + bc0;   stride = MTOT; } \
            rb0 = *(const float4*)s0;                                            \
            rb1 = *(const float4*)(s0 + stride);                                 \
        } else {                                                                 \
            const float* s0 = g_h1 + (size_t)k0 * MTOT + j0 + bc0;               \
            rb0 = *(const float4*)s0;                                            \
            rb1 = *(const float4*)(s0 + MTOT);                                   \
            float2 q0 = g_ss1[k0], q1 = g_ss1[k0 + 1];                           \
            rb0.x = fmaxf(fmaf(rb0.x, q0.x, q0.y), 0.0f);                        \
            rb0.y = fmaxf(fmaf(rb0.y, q0.x, q0.y), 0.0f);                        \
            rb0.z = fmaxf(fmaf(rb0.z, q0.x, q0.y), 0.0f);                        \
            rb0.w = fmaxf(fmaf(rb0.w, q0.x, q0.y), 0.0f);                        \
            rb1.x = fmaxf(fmaf(rb1.x, q1.x, q1.y), 0.0f);                        \
            rb1.y = fmaxf(fmaf(rb1.y, q1.x, q1.y), 0.0f);                        \
            rb1.z = fmaxf(fmaf(rb1.z, q1.x, q1.y), 0.0f);                        \
            rb1.w = fmaxf(fmaf(rb1.w, q1.x, q1.y), 0.0f);                        \
        }                                                                        \
    }

    #define STS_TILE(buf)                                                       \
    {                                                                            \
        *(uint4*)&As_hi[buf][arow * 8 + akh * 4] = ra_hi;                        \
        *(uint4*)&As_lo[buf][arow * 8 + akh * 4] = ra_lo;                        \
        uint32_t ph[4], pl[4];                                                   \
        const float* x0 = &rb0.x; const float* x1 = &rb1.x;                      \
        _Pragma("unroll")                                                        \
        for (int e = 0; e < 4; e++) {                                            \
            __nv_bfloat16 h0, l0, h1, l1;                                        \
            bf16_split(x0[e], h0, l0);                                           \
            bf16_split(x1[e], h1, l1);                                           \
            ph[e] = pack2(h0, h1);                                               \
            pl[e] = pack2(l0, l1);                                               \
        }                                                                        \
        int col = bc0 ^ (brp << 3);                                              \
        *(uint4*)&Bs_hi[buf][brp * 128 + col] = *(uint4*)ph;                     \
        *(uint4*)&Bs_lo[buf][brp * 128 + col] = *(uint4*)pl;                     \
    }

    #define COMPUTE(buf)                                                         \
    {                                                                            \
        uint32_t bh[4][2], bl[4][2];                                             \
        _Pragma("unroll")                                                        \
        for (int nt = 0; nt < 4; nt++) {                                         \
            int n = wn * 32 + nt * 8 + g;                                        \
            bh[nt][0] = Bs_hi[buf][t * 128 + (n ^ (t << 3))];                    \
            bh[nt][1] = Bs_hi[buf][(t + 4) * 128 + (n ^ ((t + 4) << 3))];        \
            bl[nt][0] = Bs_lo[buf][t * 128 + (n ^ (t << 3))];                    \
            bl[nt][1] = Bs_lo[buf][(t + 4) * 128 + (n ^ ((t + 4) << 3))];        \
        }                                                                        \
        _Pragma("unroll")                                                        \
        for (int mt = 0; mt < 4; mt++) {                                         \
            int r = wm * 64 + mt * 16 + g;                                       \
            uint32_t ah[4], al[4];                                               \
            ah[0] = As_hi[buf][r * 8 + t];                                       \
            ah[1] = As_hi[buf][(r + 8) * 8 + t];                                 \
            ah[2] = As_hi[buf][r * 8 + t + 4];                                   \
            ah[3] = As_hi[buf][(r + 8) * 8 + t + 4];                             \
            al[0] = As_lo[buf][r * 8 + t];                                       \
            al[1] = As_lo[buf][(r + 8) * 8 + t];                                 \
            al[2] = As_lo[buf][r * 8 + t + 4];                                   \
            al[3] = As_lo[buf][(r + 8) * 8 + t + 4];                             \
            _Pragma("unroll")                                                    \
            for (int nt = 0; nt < 4; nt++) {                                     \
                mma16816(acc[mt][nt], ah, bh[nt]);                               \
                mma16816(acc[mt][nt], ah, bl[nt]);                               \
                mma16816(acc[mt][nt], al, bh[nt]);                               \
            }                                                                    \
        }                                                                        \
    }

    LDG_TILE(0);
    STS_TILE(0);
    __syncthreads();

    int buf = 0;
    for (int kt = 16; kt < K; kt += 16) {
        LDG_TILE(kt);
        COMPUTE(buf);
        STS_TILE(buf ^ 1);
        __syncthreads();
        buf ^= 1;
    }
    COMPUTE(buf);

    float* dst = (mode == 1) ? g_h1 : g_h2;
    #pragma unroll
    for (int mt = 0; mt < 4; mt++) {
        #pragma unroll
        for (int nt = 0; nt < 4; nt++) {
            int row = i0 + wm * 64 + mt * 16 + g;
            int col = j0 + wn * 32 + nt * 8 + 2 * t;
            *(float2*)&dst[(size_t)row * MTOT + col] =
                make_float2(acc[mt][nt][0], acc[mt][nt][1]);
            *(float2*)&dst[(size_t)(row + 8) * MTOT + col] =
                make_float2(acc[mt][nt][2], acc[mt][nt][3]);
        }
    }
    #undef LDG_TILE
    #undef STS_TILE
    #undef COMPUTE
}

// ---------------------------------------------------------------------------
// Kernel 4: BatchNorm stats -> per-channel (scale, shift), fp64 reduction.
//   Bias terms cancel exactly inside BN, so GEMMs run bias-free.
// ---------------------------------------------------------------------------
__global__ void __launch_bounds__(256) bn_stats_kernel(
    const float* __restrict__ g, const float* __restrict__ beta, int which)
{
    const int c   = blockIdx.x;
    const int tid = threadIdx.x;
    const float* H = (which == 1) ? g_h1 : g_h2;
    const float4* p = (const float4*)(H + (size_t)c * MTOT);

    float s = 0.0f, sq = 0.0f;
    #pragma unroll 4
    for (int i = 0; i < MTOT / 4 / 256; i++) {
        float4 v = p[tid + i * 256];
        s  += v.x + v.y + v.z + v.w;
        sq += v.x * v.x + v.y * v.y + v.z * v.z + v.w * v.w;
    }

    __shared__ double r1[256], r2[256];
    r1[tid] = (double)s;
    r2[tid] = (double)sq;
    __syncthreads();
    for (int o = 128; o > 0; o >>= 1) {
        if (tid < o) { r1[tid] += r1[tid + o]; r2[tid] += r2[tid + o]; }
        __syncthreads();
    }
    if (tid == 0) {
        double mean = r1[0] / (double)MTOT;
        double var  = r2[0] / (double)MTOT - mean * mean;
        double rs   = 1.0 / sqrt(var + 1e-5);
        float scale = (float)((double)g[c] * rs);
        float shift = (float)((double)beta[c] - mean * (double)g[c] * rs);
        if (which == 1) g_ss1[c] = make_float2(scale, shift);
        else            g_ss2[c] = make_float2(scale, shift);
    }
}

// ---------------------------------------------------------------------------
// Kernel 5: final BN2 + ReLU + layout transform [c][b*N+n] -> [b][c][n]
// ---------------------------------------------------------------------------
__global__ void __launch_bounds__(256) bn_out_kernel(float* __restrict__ out)
{
    size_t f = (size_t)blockIdx.x * blockDim.x + threadIdx.x;
    size_t e = f * 4;
    int c = (int)(e / MTOT);
    int m = (int)(e % MTOT);
    int b = m / NPTS;
    int n = m % NPTS;

    float4 v = ((const float4*)g_h2)[f];
    float2 ss = g_ss2[c];
    v.x = fmaxf(fmaf(v.x, ss.x, ss.y), 0.0f);
    v.y = fmaxf(fmaf(v.y, ss.x, ss.y), 0.0f);
    v.z = fmaxf(fmaf(v.z, ss.x, ss.y), 0.0f);
    v.w = fmaxf(fmaf(v.w, ss.x, ss.y), 0.0f);
    *(float4*)(out + ((size_t)b * C3 + c) * NPTS + n) = v;
}

// ---------------------------------------------------------------------------
// Launcher
// ---------------------------------------------------------------------------
extern "C" void kernel_launch(void* const* d_in, const int* in_sizes, int n_in,
                              void* d_out, int out_size)
{
    const float* pp    = (const float*)d_in[0];   // [8,3,8192]
    const float* spp   = (const float*)d_in[1];   // [8,3,2048]
    const float* skip  = (const float*)d_in[2];   // [8,128,8192]
    const float* sfeat = (const float*)d_in[3];   // [8,256,2048]
    const float* W1    = (const float*)d_in[4];   // [256,384]
    // d_in[5] = b1 (cancels inside BN)
    const float* g1    = (const float*)d_in[6];
    const float* be1   = (const float*)d_in[7];
    const float* W2    = (const float*)d_in[8];   // [128,256]
    // d_in[9] = b2 (cancels inside BN)
    const float* g2    = (const float*)d_in[10];
    const float* be2   = (const float*)d_in[11];
    float* out = (float*)d_out;

    // 0) split weights to bf16 hi/lo
    prep_weights_kernel<<<(C2 * C1 + 255) / 256, 256>>>(W1, W2);

    // 1) 3-NN + sfeat transpose
    knn_kernel<<<B_ * (NPTS / 256), 256>>>(pp, spp);
    {
        dim3 grid(NS / 32, D2 / 32, B_), blk(32, 8);
        transpose_sfeat_kernel<<<grid, blk>>>(sfeat);
    }

    // 2) interpolation -> g_interp [c][m]
    interp_kernel<<<MTOT / 32, 256>>>();

    // 3) GEMM1 (tensor cores): H1 = W1 @ [skip ; interp]  (256 x 65536, K=384)
    {
        dim3 grid(MTOT / 128, C2 / 128);
        mma_gemm_kernel<<<grid, 256>>>(skip, C1, 1);
    }

    // 4) BN1 stats
    bn_stats_kernel<<<C2, 256>>>(g1, be1, 1);

    // 5) GEMM2 (tensor cores): H2 = W2 @ relu(BN1(H1))    (128 x 65536, K=256)
    {
        dim3 grid(MTOT / 128, C3 / 128);
        mma_gemm_kernel<<<grid, 256>>>(nullptr, C2, 2);
    }

    // 6) BN2 stats
    bn_stats_kernel<<<C3, 256>>>(g2, be2, 2);

    // 7) BN2 apply + ReLU + transpose to [B,128,N]
    bn_out_kernel<<<(C3 * MTOT / 4) / 256, 256>>>(out);
}

// round 7
// speedup vs baseline: 2.9694x; 1.3816x over previous
#include <cuda_runtime.h>
#include <cuda_fp16.h>
#include <float.h>
#include <math.h>
#include <stdint.h>

// Problem constants
#define B_    8
#define NPTS  8192
#define NS    2048
#define D1    128
#define D2    256
#define C1    384      // D1 + D2
#define C2    256
#define C3    128
#define MTOT  (B_ * NPTS)   // 65536
#define GRIDX (MTOT / 128)  // 512 column blocks per GEMM

// ---------------------------------------------------------------------------
// Scratch (static device globals — no allocations allowed)
// ---------------------------------------------------------------------------
__device__ float  g_interp[(size_t)D2 * MTOT];   // 64 MB  interpolated features [c][m]
__device__ float  g_h1[(size_t)C2 * MTOT];       // 64 MB  GEMM1 out (pre-BN)    [c][m]
__device__ float  g_h2[(size_t)C3 * MTOT];       // 32 MB  GEMM2 out (pre-BN)    [c][m]
__device__ float  g_sfT[(size_t)B_ * NS * D2];   // 16 MB  sfeat transposed [b][s][c]
__device__ float4 g_w[MTOT];                     // per-point 3-NN weights
__device__ int4   g_i[MTOT];                     // per-point 3-NN indices
__device__ float2 g_ss1[C2];                     // BN1 (scale, shift)
__device__ float2 g_ss2[C3];                     // BN2 (scale, shift)
// fp16 weights, row-major [o][k]; 16B-aligned for uint4 loads
__device__ __align__(16) __half g_W1h[C2 * C1];
__device__ __align__(16) __half g_W2h[C3 * C2];
// per-block BN partial stats (deterministic two-stage reduction, no atomics)
__device__ float g_psA[C2 * GRIDX], g_pqA[C2 * GRIDX];   // GEMM1 sums / sumsqs
__device__ float g_psB[C3 * GRIDX], g_pqB[C3 * GRIDX];   // GEMM2 sums / sumsqs

__device__ __forceinline__ void mma16816(float* d, const uint32_t* a, const uint32_t* b) {
    asm volatile(
        "mma.sync.aligned.m16n8k16.row.col.f32.f16.f16.f32 "
        "{%0,%1,%2,%3}, {%4,%5,%6,%7}, {%8,%9}, {%0,%1,%2,%3};\n"
        : "+f"(d[0]), "+f"(d[1]), "+f"(d[2]), "+f"(d[3])
        : "r"(a[0]), "r"(a[1]), "r"(a[2]), "r"(a[3]), "r"(b[0]), "r"(b[1]));
}

// ---------------------------------------------------------------------------
// Kernel 0: convert weights to fp16
// ---------------------------------------------------------------------------
__global__ void __launch_bounds__(256) prep_weights_kernel(
    const float* __restrict__ W1, const float* __restrict__ W2)
{
    int i = blockIdx.x * 256 + threadIdx.x;
    if (i < C2 * C1) g_W1h[i] = __float2half_rn(W1[i]);
    if (i < C3 * C2) g_W2h[i] = __float2half_rn(W2[i]);
}

// ---------------------------------------------------------------------------
// Kernel 1: 3-NN search (indices + normalized inverse-distance weights)
// ---------------------------------------------------------------------------
__global__ void __launch_bounds__(256) knn_kernel(
    const float* __restrict__ pp,     // [B,3,N]
    const float* __restrict__ spp)    // [B,3,S]
{
    __shared__ float4 ssmp[NS];       // 32 KB

    const int b   = blockIdx.x >> 5;
    const int n0  = (blockIdx.x & 31) << 8;
    const int tid = threadIdx.x;

    const float* sb = spp + (size_t)b * 3 * NS;
    for (int s = tid; s < NS; s += 256) {
        float x = sb[s], y = sb[s + NS], z = sb[s + 2 * NS];
        ssmp[s] = make_float4(x, y, z, fmaf(x, x, fmaf(y, y, z * z)));
    }
    __syncthreads();

    const int n = n0 + tid;
    const int m = b * NPTS + n;
    const float* pb = pp + (size_t)b * 3 * NPTS;
    const float px = pb[n], py = pb[n + NPTS], pz = pb[n + 2 * NPTS];

    float d0 = FLT_MAX, d1 = FLT_MAX, d2 = FLT_MAX;
    int   i0 = 0, i1 = 0, i2 = 0;

    #pragma unroll 4
    for (int j = 0; j < NS; j++) {
        float4 q   = ssmp[j];
        float  dot = fmaf(px, q.x, fmaf(py, q.y, pz * q.z));
        float  sc  = fmaf(-2.0f, dot, q.w);
        if (sc < d2) {
            if (sc < d1) {
                d2 = d1; i2 = i1;
                if (sc < d0) { d1 = d0; i1 = i0; d0 = sc; i0 = j; }
                else         { d1 = sc; i1 = j; }
            } else { d2 = sc; i2 = j; }
        }
    }

    const float p2 = fmaf(px, px, fmaf(py, py, pz * pz));
    float a0 = 1.0f / ((d0 + p2) + 1e-8f);
    float a1 = 1.0f / ((d1 + p2) + 1e-8f);
    float a2 = 1.0f / ((d2 + p2) + 1e-8f);
    const float inv = 1.0f / (a0 + a1 + a2);

    g_w[m] = make_float4(a0 * inv, a1 * inv, a2 * inv, 0.0f);
    g_i[m] = make_int4(i0, i1, i2, 0);
}

// ---------------------------------------------------------------------------
// Kernel 1b: transpose sfeat [b][c][s] -> g_sfT [b][s][c]
// ---------------------------------------------------------------------------
__global__ void __launch_bounds__(256) transpose_sfeat_kernel(
    const float* __restrict__ sfeat)
{
    __shared__ float tile[32][33];
    const int b  = blockIdx.z;
    const int s0 = blockIdx.x * 32;
    const int c0 = blockIdx.y * 32;
    const int tx = threadIdx.x;
    const int ty = threadIdx.y;

    #pragma unroll
    for (int r = 0; r < 32; r += 8)
        tile[ty + r][tx] = sfeat[((size_t)b * D2 + c0 + ty + r) * NS + s0 + tx];
    __syncthreads();
    #pragma unroll
    for (int r = 0; r < 32; r += 8)
        g_sfT[((size_t)b * NS + s0 + ty + r) * D2 + c0 + tx] = tile[tx][ty + r];
}

// ---------------------------------------------------------------------------
// Kernel 2: coalesced interpolation -> g_interp [c][m]
// ---------------------------------------------------------------------------
__global__ void __launch_bounds__(256) interp_kernel()
{
    __shared__ float  st[D2][33];
    __shared__ float4 sw[32];
    __shared__ int4   si[32];

    const int m0  = blockIdx.x * 32;
    const int b   = m0 / NPTS;
    const int tid = threadIdx.x;

    if (tid < 32) { sw[tid] = g_w[m0 + tid]; si[tid] = g_i[m0 + tid]; }
    __syncthreads();

    const float* fT = g_sfT + (size_t)b * NS * D2;
    #pragma unroll 4
    for (int p = 0; p < 32; p++) {
        float4 w = sw[p];
        int4   ii = si[p];
        float v = fmaf(w.x, __ldg(fT + (size_t)ii.x * D2 + tid),
                  fmaf(w.y, __ldg(fT + (size_t)ii.y * D2 + tid),
                       w.z * __ldg(fT + (size_t)ii.z * D2 + tid)));
        st[tid][p] = v;
    }
    __syncthreads();

    const int c8 = tid >> 3;
    const int j  = (tid & 7) << 2;
    #pragma unroll
    for (int r = 0; r < 8; r++) {
        int c = r * 32 + c8;
        float4 v = make_float4(st[c][j], st[c][j + 1], st[c][j + 2], st[c][j + 3]);
        *(float4*)&g_interp[(size_t)c * MTOT + m0 + j] = v;
    }
}

// ---------------------------------------------------------------------------
// Kernel 3: tensor-core GEMM, single fp16 mma per k16-step.
//   C[i][j] = sum_k W[i][k] * Bsrc[k][j]
//   128x128 tile, BK=16, 8 warps (2x4), warp tile 64x32, mma.m16n8k16 f16.
//   Epilogue additionally emits per-block per-channel (sum, sumsq) partials
//   for the BatchNorm stats (reduced by bn_reduce_kernel; deterministic).
//   mode 1: W1; Bsrc k<128 from skip, k>=128 from g_interp. Out g_h1.
//   mode 2: W2; Bsrc = relu(g_h1*scale1+shift1) fused.       Out g_h2.
// ---------------------------------------------------------------------------
__global__ void __launch_bounds__(256) mma_gemm_kernel(
    const float* __restrict__ skip,   // mode 1 only
    int K, int mode)
{
    __shared__ uint32_t As[2][128 * 8];   // [m][kpair]  half2 entries, 4KB/buf
    __shared__ uint32_t Bs[2][8 * 128];   // [kpair][n ^ (kp<<3)]       4KB/buf

    const __half* __restrict__ Wh = (mode == 1) ? g_W1h : g_W2h;

    const int tid  = threadIdx.x;
    const int lane = tid & 31;
    const int wid  = tid >> 5;
    const int wm   = wid >> 2;        // 0..1
    const int wn   = wid & 3;         // 0..3
    const int g    = lane >> 2;       // 0..7
    const int t    = lane & 3;        // 0..3

    const int j0 = blockIdx.x * 128;
    const int i0 = blockIdx.y * 128;

    const int arow = tid >> 1;            // A: row 0..127
    const int akh  = tid & 1;             // A: k-half (8 halfs)
    const int brp  = tid >> 5;            // B: k-pair row 0..7
    const int bc0  = lane * 4;            // B: col group

    const int bb  = j0 / NPTS;
    const int nn0 = j0 % NPTS;

    float acc[4][4][4];
    #pragma unroll
    for (int mt = 0; mt < 4; mt++)
        #pragma unroll
        for (int nt = 0; nt < 4; nt++)
            #pragma unroll
            for (int e = 0; e < 4; e++) acc[mt][nt][e] = 0.0f;

    uint4  ra;
    float4 rb0, rb1;

    #define LDG_TILE(kt)                                                         \
    {                                                                            \
        ra = *(const uint4*)(Wh + (size_t)(i0 + arow) * K + (kt) + akh * 8);     \
        int k0 = (kt) + brp * 2;                                                 \
        if (mode == 1) {                                                         \
            const float* s0; size_t stride;                                      \
            if (k0 < D1) { s0 = skip + ((size_t)bb * D1 + k0) * NPTS + nn0 + bc0; stride = NPTS; } \
            else         { s0 = g_interp + (size_t)(k0 - D1) * MTOT + j0 + bc0;   stride = MTOT; } \
            rb0 = *(const float4*)s0;                                            \
            rb1 = *(const float4*)(s0 + stride);                                 \
        } else {                                                                 \
            const float* s0 = g_h1 + (size_t)k0 * MTOT + j0 + bc0;               \
            rb0 = *(const float4*)s0;                                            \
            rb1 = *(const float4*)(s0 + MTOT);                                   \
            float2 q0 = g_ss1[k0], q1 = g_ss1[k0 + 1];                           \
            rb0.x = fmaxf(fmaf(rb0.x, q0.x, q0.y), 0.0f);                        \
            rb0.y = fmaxf(fmaf(rb0.y, q0.x, q0.y), 0.0f);                        \
            rb0.z = fmaxf(fmaf(rb0.z, q0.x, q0.y), 0.0f);                        \
            rb0.w = fmaxf(fmaf(rb0.w, q0.x, q0.y), 0.0f);                        \
            rb1.x = fmaxf(fmaf(rb1.x, q1.x, q1.y), 0.0f);                        \
            rb1.y = fmaxf(fmaf(rb1.y, q1.x, q1.y), 0.0f);                        \
            rb1.z = fmaxf(fmaf(rb1.z, q1.x, q1.y), 0.0f);                        \
            rb1.w = fmaxf(fmaf(rb1.w, q1.x, q1.y), 0.0f);                        \
        }                                                                        \
    }

    #define STS_TILE(buf)                                                       \
    {                                                                            \
        *(uint4*)&As[buf][arow * 8 + akh * 4] = ra;                              \
        uint32_t ph[4];                                                          \
        const float* x0 = &rb0.x; const float* x1 = &rb1.x;                      \
        _Pragma("unroll")                                                        \
        for (int e = 0; e < 4; e++) {                                            \
            __half2 h = __floats2half2_rn(x0[e], x1[e]);  /* lo = k even */      \
            ph[e] = *reinterpret_cast<uint32_t*>(&h);                            \
        }                                                                        \
        int col = bc0 ^ (brp << 3);                                              \
        *(uint4*)&Bs[buf][brp * 128 + col] = *(uint4*)ph;                        \
    }

    #define COMPUTE(buf)                                                         \
    {                                                                            \
        uint32_t bf[4][2];                                                       \
        _Pragma("unroll")                                                        \
        for (int nt = 0; nt < 4; nt++) {                                         \
            int n = wn * 32 + nt * 8 + g;                                        \
            bf[nt][0] = Bs[buf][t * 128 + (n ^ (t << 3))];                       \
            bf[nt][1] = Bs[buf][(t + 4) * 128 + (n ^ ((t + 4) << 3))];           \
        }                                                                        \
        _Pragma("unroll")                                                        \
        for (int mt = 0; mt < 4; mt++) {                                         \
            int r = wm * 64 + mt * 16 + g;                                       \
            uint32_t ah[4];                                                      \
            ah[0] = As[buf][r * 8 + t];                                          \
            ah[1] = As[buf][(r + 8) * 8 + t];                                    \
            ah[2] = As[buf][r * 8 + t + 4];                                      \
            ah[3] = As[buf][(r + 8) * 8 + t + 4];                                \
            _Pragma("unroll")                                                    \
            for (int nt = 0; nt < 4; nt++)                                       \
                mma16816(acc[mt][nt], ah, bf[nt]);                               \
        }                                                                        \
    }

    LDG_TILE(0);
    STS_TILE(0);
    __syncthreads();

    int buf = 0;
    for (int kt = 16; kt < K; kt += 16) {
        LDG_TILE(kt);
        COMPUTE(buf);
        STS_TILE(buf ^ 1);
        __syncthreads();
        buf ^= 1;
    }
    COMPUTE(buf);

    // ---- store C tile ----
    float* dst = (mode == 1) ? g_h1 : g_h2;
    #pragma unroll
    for (int mt = 0; mt < 4; mt++) {
        #pragma unroll
        for (int nt = 0; nt < 4; nt++) {
            int row = i0 + wm * 64 + mt * 16 + g;
            int col = j0 + wn * 32 + nt * 8 + 2 * t;
            *(float2*)&dst[(size_t)row * MTOT + col] =
                make_float2(acc[mt][nt][0], acc[mt][nt][1]);
            *(float2*)&dst[(size_t)(row + 8) * MTOT + col] =
                make_float2(acc[mt][nt][2], acc[mt][nt][3]);
        }
    }

    // ---- per-block BN partial stats (sum, sumsq per channel-row) ----
    __syncthreads();                      // done reading As/Bs; reuse as float
    float* Ssum = (float*)As;             // [16][128]
    float* Ssq  = (float*)Bs;             // [16][128]
    const int ci = wn * 4 + t;            // 16 column-groups
    #pragma unroll
    for (int mt = 0; mt < 4; mt++) {
        int r0 = wm * 64 + mt * 16 + g;
        float s0 = 0.f, q0 = 0.f, s1 = 0.f, q1 = 0.f;
        #pragma unroll
        for (int nt = 0; nt < 4; nt++) {
            float e0 = acc[mt][nt][0], e1 = acc[mt][nt][1];
            float e2 = acc[mt][nt][2], e3 = acc[mt][nt][3];
            s0 += e0 + e1;  q0 += e0 * e0 + e1 * e1;
            s1 += e2 + e3;  q1 += e2 * e2 + e3 * e3;
        }
        Ssum[ci * 128 + r0]     = s0;  Ssq[ci * 128 + r0]     = q0;
        Ssum[ci * 128 + r0 + 8] = s1;  Ssq[ci * 128 + r0 + 8] = q1;
    }
    __syncthreads();

    float* psum = (mode == 1) ? g_psA : g_psB;
    float* psq  = (mode == 1) ? g_pqA : g_pqB;
    if (tid < 128) {
        float s = 0.f;
        #pragma unroll
        for (int c = 0; c < 16; c++) s += Ssum[c * 128 + tid];
        psum[(size_t)(i0 + tid) * GRIDX + blockIdx.x] = s;
    } else {
        int r = tid - 128;
        float q = 0.f;
        #pragma unroll
        for (int c = 0; c < 16; c++) q += Ssq[c * 128 + r];
        psq[(size_t)(i0 + r) * GRIDX + blockIdx.x] = q;
    }
    #undef LDG_TILE
    #undef STS_TILE
    #undef COMPUTE
}

// ---------------------------------------------------------------------------
// Kernel 4: reduce per-block partials -> per-channel (scale, shift).
//   Deterministic (fixed order), fp64 accumulation. Bias cancels inside BN.
// ---------------------------------------------------------------------------
__global__ void __launch_bounds__(256) bn_reduce_kernel(
    const float* __restrict__ g, const float* __restrict__ beta, int which)
{
    const int c   = blockIdx.x;
    const int tid = threadIdx.x;
    const float* ps = (which == 1) ? g_psA : g_psB;
    const float* pq = (which == 1) ? g_pqA : g_pqB;

    double s = (double)ps[(size_t)c * GRIDX + tid] + (double)ps[(size_t)c * GRIDX + tid + 256];
    double q = (double)pq[(size_t)c * GRIDX + tid] + (double)pq[(size_t)c * GRIDX + tid + 256];

    __shared__ double r1[256], r2[256];
    r1[tid] = s;  r2[tid] = q;
    __syncthreads();
    for (int o = 128; o > 0; o >>= 1) {
        if (tid < o) { r1[tid] += r1[tid + o]; r2[tid] += r2[tid + o]; }
        __syncthreads();
    }
    if (tid == 0) {
        double mean = r1[0] / (double)MTOT;
        double var  = r2[0] / (double)MTOT - mean * mean;
        double rs   = 1.0 / sqrt(var + 1e-5);
        float scale = (float)((double)g[c] * rs);
        float shift = (float)((double)beta[c] - mean * (double)g[c] * rs);
        if (which == 1) g_ss1[c] = make_float2(scale, shift);
        else            g_ss2[c] = make_float2(scale, shift);
    }
}

// ---------------------------------------------------------------------------
// Kernel 5: final BN2 + ReLU + layout transform [c][b*N+n] -> [b][c][n]
// ---------------------------------------------------------------------------
__global__ void __launch_bounds__(256) bn_out_kernel(float* __restrict__ out)
{
    size_t f = (size_t)blockIdx.x * blockDim.x + threadIdx.x;
    size_t e = f * 4;
    int c = (int)(e / MTOT);
    int m = (int)(e % MTOT);
    int b = m / NPTS;
    int n = m % NPTS;

    float4 v = ((const float4*)g_h2)[f];
    float2 ss = g_ss2[c];
    v.x = fmaxf(fmaf(v.x, ss.x, ss.y), 0.0f);
    v.y = fmaxf(fmaf(v.y, ss.x, ss.y), 0.0f);
    v.z = fmaxf(fmaf(v.z, ss.x, ss.y), 0.0f);
    v.w = fmaxf(fmaf(v.w, ss.x, ss.y), 0.0f);
    *(float4*)(out + ((size_t)b * C3 + c) * NPTS + n) = v;
}

// ---------------------------------------------------------------------------
// Launcher
// ---------------------------------------------------------------------------
extern "C" void kernel_launch(void* const* d_in, const int* in_sizes, int n_in,
                              void* d_out, int out_size)
{
    const float* pp    = (const float*)d_in[0];   // [8,3,8192]
    const float* spp   = (const float*)d_in[1];   // [8,3,2048]
    const float* skip  = (const float*)d_in[2];   // [8,128,8192]
    const float* sfeat = (const float*)d_in[3];   // [8,256,2048]
    const float* W1    = (const float*)d_in[4];   // [256,384]
    // d_in[5] = b1 (cancels inside BN)
    const float* g1    = (const float*)d_in[6];
    const float* be1   = (const float*)d_in[7];
    const float* W2    = (const float*)d_in[8];   // [128,256]
    // d_in[9] = b2 (cancels inside BN)
    const float* g2    = (const float*)d_in[10];
    const float* be2   = (const float*)d_in[11];
    float* out = (float*)d_out;

    // 0) weights -> fp16
    prep_weights_kernel<<<(C2 * C1 + 255) / 256, 256>>>(W1, W2);

    // 1) 3-NN + sfeat transpose
    knn_kernel<<<B_ * (NPTS / 256), 256>>>(pp, spp);
    {
        dim3 grid(NS / 32, D2 / 32, B_), blk(32, 8);
        transpose_sfeat_kernel<<<grid, blk>>>(sfeat);
    }

    // 2) interpolation -> g_interp [c][m]
    interp_kernel<<<MTOT / 32, 256>>>();

    // 3) GEMM1 (+BN1 partial stats): H1 = W1 @ [skip ; interp]
    {
        dim3 grid(GRIDX, C2 / 128);
        mma_gemm_kernel<<<grid, 256>>>(skip, C1, 1);
    }
    bn_reduce_kernel<<<C2, 256>>>(g1, be1, 1);

    // 4) GEMM2 (+BN2 partial stats): H2 = W2 @ relu(BN1(H1))
    {
        dim3 grid(GRIDX, C3 / 128);
        mma_gemm_kernel<<<grid, 256>>>(nullptr, C2, 2);
    }
    bn_reduce_kernel<<<C3, 256>>>(g2, be2, 2);

    // 5) BN2 apply + ReLU + transpose to [B,128,N]
    bn_out_kernel<<<(C3 * MTOT / 4) / 256, 256>>>(out);
}